// round 7
// baseline (speedup 1.0000x reference)
#include <cuda_runtime.h>
#include <cstdint>

#define LSEQ 200
#define LP   68
#define NTHR 384

// ---- smem float offsets ----
#define OFF_MS   0              // A tf32 [200][68], later Ms
#define OFF_BF   13600          // B fragments 8*8*66 = 4224 (dead after MMA)
#define OFF_WTSI OFF_BF         // [200][4] = 800
#define OFF_PART (OFF_BF+800)   // [24][3][64] = 4608
#define OFF_CAND (OFF_BF+5408)  // [192]
#define OFF_FAC  (OFF_BF+5600)  // [4]
#define SMEM_FLOATS (OFF_BF + 5604)   // 19204 floats = 76816 B -> 2 CTAs/SM

__device__ __forceinline__ uint32_t to_tf32(float x) {
    uint32_t u;
    asm("cvt.rna.tf32.f32 %0, %1;" : "=r"(u) : "f"(x));
    return u;
}

__device__ __forceinline__ void mma_tf32(float& c0, float& c1, float& c2, float& c3,
                                         uint32_t a0, uint32_t a1, uint32_t a2, uint32_t a3,
                                         uint32_t b0, uint32_t b1) {
    asm volatile("mma.sync.aligned.m16n8k8.row.col.f32.tf32.tf32.f32 "
                 "{%0,%1,%2,%3}, {%4,%5,%6,%7}, {%8,%9}, {%0,%1,%2,%3};"
                 : "+f"(c0), "+f"(c1), "+f"(c2), "+f"(c3)
                 : "r"(a0), "r"(a1), "r"(a2), "r"(a3), "r"(b0), "r"(b1));
}

__device__ __forceinline__ float2 ffma2(float2 a, float2 b, float2 c) {
    float2 r;
    asm("fma.rn.f32x2 %0, %1, %2, %3;"
        : "=l"(reinterpret_cast<unsigned long long&>(r))
        : "l"(reinterpret_cast<unsigned long long&>(a)),
          "l"(reinterpret_cast<unsigned long long&>(b)),
          "l"(reinterpret_cast<unsigned long long&>(c)));
    return r;
}

__global__ __launch_bounds__(NTHR, 2)
void caps_kernel(const float* __restrict__ E,
                 const float* __restrict__ Wg,
                 const float* __restrict__ Lg,
                 const int*   __restrict__ SL,
                 float* __restrict__ out)
{
    extern __shared__ float sm[];
    const int n = blockIdx.x;
    const int t = threadIdx.x;
    const int wid = t >> 5, lane = t & 31;

    // ---- stage B fragments: tile (nb,kb) = 66 floats ----
    {
        const float4* w4 = reinterpret_cast<const float4*>(Wg);
        #pragma unroll
        for (int i = 0; i < 3; i++) {
            const int f = t + NTHR*i;             // f < 1024
            if (f < 1024) {
                const int d = f >> 4;
                const float4 v = w4[f];
                const float vv[4] = { v.x, v.y, v.z, v.w };
                #pragma unroll
                for (int j = 0; j < 4; j++) {
                    const int o = 4*(f & 15) + j;
                    const int nb = o >> 3, kb = d >> 3;
                    const int ln = ((o & 7) << 2) | (d & 3);
                    const int slot = ((d & 7) >> 2);
                    sm[OFF_BF + (nb*8 + kb)*66 + ln*2 + slot] =
                        __uint_as_float(to_tf32(vv[j]));
                }
            }
        }
    }

    // ---- stage A row-major [200][68] (tf32), vectorized ----
    {
        const float4* e4 = reinterpret_cast<const float4*>(E + (size_t)n * LSEQ * 64);
        #pragma unroll
        for (int i = 0; i < 9; i++) {
            const int f = t + NTHR*i;             // f < 3200
            if (f < 3200) {
                const int l = f >> 4, q = f & 15;
                const float4 v = e4[f];
                uint4 u;
                u.x = to_tf32(v.x); u.y = to_tf32(v.y);
                u.z = to_tf32(v.z); u.w = to_tf32(v.w);
                *reinterpret_cast<uint4*>(sm + OFF_MS + l*LP + 4*q) = u;
            }
        }
    }

    // logits in registers: thread t owns position l = t (t < 200)
    const bool haveL = (t < LSEQ);
    float lg0 = 0.f, lg1 = 0.f, lg2 = 0.f;
    if (haveL) {
        const float* lgp = Lg + n*600 + t;
        lg0 = lgp[0]; lg1 = lgp[200]; lg2 = lgp[400];
    }
    const int sl = SL[n];
    __syncthreads();

    // ---- Phase B mma: 12 warps = 6 wm-groups x 2 wn-halves ----
    const int wm = wid >> 1, wn = wid & 1;
    const int mb_base = 2*wm;                     // wm<5: {2wm,2wm+1}; wm=5: {10,11,12}
    const int mbcnt   = (wm == 5) ? 3 : 2;
    const int r_lo = lane >> 2, c_lo = lane & 3;

    float acc[3][4][4];
    #pragma unroll
    for (int a = 0; a < 3; a++)
        #pragma unroll
        for (int b = 0; b < 4; b++)
            #pragma unroll
            for (int c = 0; c < 4; c++) acc[a][b][c] = 0.f;

    #pragma unroll
    for (int kb = 0; kb < 8; kb++) {
        uint32_t bf[4][2];
        #pragma unroll
        for (int nbl = 0; nbl < 4; nbl++) {
            const int nb = wn*4 + nbl;
            const uint2 bv = *reinterpret_cast<const uint2*>(
                sm + OFF_BF + (nb*8 + kb)*66 + lane*2);
            bf[nbl][0] = bv.x; bf[nbl][1] = bv.y;
        }
        #pragma unroll
        for (int mbl = 0; mbl < 3; mbl++) {
            if (mbl < mbcnt) {
                const int mb = mb_base + mbl;
                const float* Ap = sm + OFF_MS + (mb*16 + r_lo)*LP + kb*8 + c_lo;
                const uint32_t a0 = __float_as_uint(Ap[0]);
                const uint32_t a1 = __float_as_uint(Ap[8*LP]);
                const uint32_t a2 = __float_as_uint(Ap[4]);
                const uint32_t a3 = __float_as_uint(Ap[8*LP + 4]);
                #pragma unroll
                for (int nbl = 0; nbl < 4; nbl++)
                    mma_tf32(acc[mbl][nbl][0], acc[mbl][nbl][1],
                             acc[mbl][nbl][2], acc[mbl][nbl][3],
                             a0, a1, a2, a3, bf[nbl][0], bf[nbl][1]);
            }
        }
    }
    __syncthreads();   // MMA reads done; A region becomes Ms, BF becomes Phase-C pool

    // ---- epilogue: accum -> Ms[l][LP] ----
    {
        const int cbase = 2*c_lo;
        #pragma unroll
        for (int mbl = 0; mbl < 3; mbl++) {
            if (mbl < mbcnt) {
                const int mb = mb_base + mbl;
                const int r0 = mb*16 + r_lo, r1 = r0 + 8;
                #pragma unroll
                for (int nbl = 0; nbl < 4; nbl++) {
                    const int nn = (wn*4 + nbl)*8 + cbase;
                    if (r0 < LSEQ)
                        *reinterpret_cast<float2*>(sm + OFF_MS + r0*LP + nn) =
                            make_float2(acc[mbl][nbl][0], acc[mbl][nbl][1]);
                    if (r1 < LSEQ)
                        *reinterpret_cast<float2*>(sm + OFF_MS + r1*LP + nn) =
                            make_float2(acc[mbl][nbl][2], acc[mbl][nbl][3]);
                }
            }
        }
    }
    __syncthreads();

    // ---- Phase C: 3 routing iterations ----
    const bool valid = (t < sl);

    #pragma unroll 1
    for (int iter = 0; iter < 3; iter++) {
        if (haveL) {
            float w0, w1, w2;
            if (valid) {
                const float m  = fmaxf(lg0, fmaxf(lg1, lg2));
                const float e0 = __expf(lg0 - m), e1 = __expf(lg1 - m), e2 = __expf(lg2 - m);
                const float inv = __frcp_rn(e0 + e1 + e2);
                w0 = e0*inv; w1 = e1*inv; w2 = e2*inv;
            } else {
                w0 = w1 = w2 = (1.f/3.f);
            }
            *reinterpret_cast<float4*>(sm + OFF_WTSI + 4*t) = make_float4(w0, w1, w2, 0.f);
        }
        __syncthreads();

        // candidate partials: 24 lq-groups x 16 o4-groups; each covers 9 l's
        {
            const int o4 = t & 15, lq = t >> 4;   // lq 0..23
            float2 c[3][2];
            #pragma unroll
            for (int k = 0; k < 3; k++) { c[k][0] = make_float2(0.f,0.f); c[k][1] = make_float2(0.f,0.f); }
            const int l0 = lq*9;
            #pragma unroll
            for (int j = 0; j < 9; j++) {
                const int l = l0 + j;
                if (l < LSEQ) {
                    const float4 m4 = *reinterpret_cast<const float4*>(sm + OFF_MS + l*LP + 4*o4);
                    const float4 wv = *reinterpret_cast<const float4*>(sm + OFF_WTSI + 4*l);
                    const float2 mlo = make_float2(m4.x, m4.y), mhi = make_float2(m4.z, m4.w);
                    c[0][0] = ffma2(make_float2(wv.x, wv.x), mlo, c[0][0]);
                    c[0][1] = ffma2(make_float2(wv.x, wv.x), mhi, c[0][1]);
                    c[1][0] = ffma2(make_float2(wv.y, wv.y), mlo, c[1][0]);
                    c[1][1] = ffma2(make_float2(wv.y, wv.y), mhi, c[1][1]);
                    c[2][0] = ffma2(make_float2(wv.z, wv.z), mlo, c[2][0]);
                    c[2][1] = ffma2(make_float2(wv.z, wv.z), mhi, c[2][1]);
                }
            }
            #pragma unroll
            for (int k = 0; k < 3; k++)
                *reinterpret_cast<float4*>(sm + OFF_PART + (lq*3 + k)*64 + 4*o4) =
                    make_float4(c[k][0].x, c[k][0].y, c[k][1].x, c[k][1].y);
        }
        __syncthreads();

        if (t < 192) {
            const int k = t >> 6, o = t & 63;
            float s = 0.f;
            #pragma unroll
            for (int lq = 0; lq < 24; lq++) s += sm[OFF_PART + (lq*3 + k)*64 + o];
            sm[OFF_CAND + t] = s;
        }
        __syncthreads();

        if (t < 96) {
            const int k = t >> 5, ln = t & 31;
            const float v1 = sm[OFF_CAND + k*64 + ln];
            const float v2 = sm[OFF_CAND + k*64 + 32 + ln];
            float s = v1*v1 + v2*v2;
            #pragma unroll
            for (int off = 16; off; off >>= 1) s += __shfl_xor_sync(0xffffffffu, s, off);
            if (ln == 0) sm[OFF_FAC + k] = s / ((1.f + s) * sqrtf(s + 1e-8f));
        }
        __syncthreads();

        if (iter < 2) {
            if (haveL) {
                const float4* ml = reinterpret_cast<const float4*>(sm + OFF_MS + t*LP);
                const float4* c0 = reinterpret_cast<const float4*>(sm + OFF_CAND);
                const float4* c1 = reinterpret_cast<const float4*>(sm + OFF_CAND + 64);
                const float4* c2 = reinterpret_cast<const float4*>(sm + OFF_CAND + 128);
                float2 a0 = make_float2(0.f,0.f), a1 = make_float2(0.f,0.f), a2 = make_float2(0.f,0.f);
                #pragma unroll 4
                for (int q = 0; q < 16; q++) {
                    const float4 m = ml[q];
                    const float2 mlo = make_float2(m.x, m.y), mhi = make_float2(m.z, m.w);
                    const float4 x0 = c0[q], x1 = c1[q], x2 = c2[q];
                    a0 = ffma2(mlo, make_float2(x0.x, x0.y), a0);
                    a0 = ffma2(mhi, make_float2(x0.z, x0.w), a0);
                    a1 = ffma2(mlo, make_float2(x1.x, x1.y), a1);
                    a1 = ffma2(mhi, make_float2(x1.z, x1.w), a1);
                    a2 = ffma2(mlo, make_float2(x2.x, x2.y), a2);
                    a2 = ffma2(mhi, make_float2(x2.z, x2.w), a2);
                }
                const float f0 = sm[OFF_FAC], f1 = sm[OFF_FAC + 1], f2 = sm[OFF_FAC + 2];
                lg0 += f0 * (a0.x + a0.y);
                lg1 += f1 * (a1.x + a1.y);
                lg2 += f2 * (a2.x + a2.y);
            }
        } else {
            if (t < 192)
                out[n*192 + t] = sm[OFF_FAC + (t >> 6)] * sm[OFF_CAND + t];
        }
    }
}

extern "C" void kernel_launch(void* const* d_in, const int* in_sizes, int n_in,
                              void* d_out, int out_size)
{
    const float* E  = (const float*)d_in[0];  // [N,200,64]
    const float* W  = (const float*)d_in[1];  // [64,64]
    const float* Lg = (const float*)d_in[2];  // [N,3,200]
    const int*   SL = (const int*)d_in[3];    // [N,1]
    float* out = (float*)d_out;               // [N,3,64]

    const int N = in_sizes[3];
    const int smem_bytes = SMEM_FLOATS * (int)sizeof(float);

    cudaFuncSetAttribute(caps_kernel,
                         cudaFuncAttributeMaxDynamicSharedMemorySize, smem_bytes);

    caps_kernel<<<N, NTHR, smem_bytes>>>(E, W, Lg, SL, out);
}